// round 3
// baseline (speedup 1.0000x reference)
#include <cuda_runtime.h>
#include <math.h>

#define B_   32
#define N_   512
#define D_   768
#define NBR_ 4
#define L_   2
#define FH_  256
#define NC_  2
#define RB_  (NBR_*B_)   // 128

#define ISD 0.0360843918243516f  // 1/sqrt(768)

// ---------------- scratch (device globals; allocation-free) ----------------
__device__ float g_Mw[NBR_*L_*D_*D_];       // Wq @ Wk^T per (branch,layer)
__device__ float g_t[NBR_*B_*N_*D_];        // feat @ Mw
__device__ float g_gate[NBR_*B_*N_*N_];     // layer-1 gate (adj)
__device__ float g_feat1[NBR_*B_*N_*D_];    // layer-1 propagated features
__device__ float g_degp [RB_*N_*4];         // layer-1 degree partials (per j-tile)
__device__ float g_disv [RB_*N_];           // layer-1 D^-1/2
__device__ float g_degp2[RB_*N_*4];         // layer-2 degree partials
__device__ float g_dis2 [RB_*N_];           // layer-2 D^-1/2
__device__ float g_gcol2[RB_*N_];           // layer-2 gate column j=511
__device__ float g_node2[RB_*D_];           // layer-2 node-511 features

// ---------------------------------------------------------------------------
// Common 128x128 tile, 256 threads, 8x8 per thread, K-tile 8.
// Thread map: tx = tid&15, ty = tid>>4.
// Rows owned: ty*4+i (i<4), 64+ty*4+(i-4). Cols same with tx.
// ---------------------------------------------------------------------------

// Mw[z] = Wq_mat[z] @ Wk_mat[z]^T   (768x768x768, NT), z in [0,8)
__global__ void __launch_bounds__(256) k_mw(const float* __restrict__ Wq,
                                            const float* __restrict__ Wk) {
    const int z = blockIdx.z;
    const float* A  = Wq + (size_t)z * D_ * D_;
    const float* Bm = Wk + (size_t)z * D_ * D_;
    float* C = g_Mw + (size_t)z * D_ * D_;
    const int m0 = blockIdx.x * 128, n0 = blockIdx.y * 128;

    __shared__ float As[8][128];
    __shared__ float Bs[8][128];
    float acc[8][8] = {};
    const int tid = threadIdx.x, tx = tid & 15, ty = tid >> 4;
    const int la_row = tid >> 1, la_k4 = (tid & 1) * 4;

    for (int k0 = 0; k0 < D_; k0 += 8) {
        float4 a4 = *(const float4*)(A + (size_t)(m0 + la_row) * D_ + k0 + la_k4);
        As[la_k4+0][la_row] = a4.x; As[la_k4+1][la_row] = a4.y;
        As[la_k4+2][la_row] = a4.z; As[la_k4+3][la_row] = a4.w;
        float4 b4 = *(const float4*)(Bm + (size_t)(n0 + la_row) * D_ + k0 + la_k4);
        Bs[la_k4+0][la_row] = b4.x; Bs[la_k4+1][la_row] = b4.y;
        Bs[la_k4+2][la_row] = b4.z; Bs[la_k4+3][la_row] = b4.w;
        __syncthreads();
        #pragma unroll
        for (int kk = 0; kk < 8; kk++) {
            float4 a0 = *(float4*)&As[kk][ty*4];
            float4 a1 = *(float4*)&As[kk][64+ty*4];
            float4 b0 = *(float4*)&Bs[kk][tx*4];
            float4 b1 = *(float4*)&Bs[kk][64+tx*4];
            float av[8] = {a0.x,a0.y,a0.z,a0.w,a1.x,a1.y,a1.z,a1.w};
            float bv[8] = {b0.x,b0.y,b0.z,b0.w,b1.x,b1.y,b1.z,b1.w};
            #pragma unroll
            for (int i = 0; i < 8; i++)
                #pragma unroll
                for (int j = 0; j < 8; j++)
                    acc[i][j] = fmaf(av[i], bv[j], acc[i][j]);
        }
        __syncthreads();
    }
    #pragma unroll
    for (int i = 0; i < 8; i++) {
        const int row = (i < 4) ? (ty*4 + i) : (64 + ty*4 + i - 4);
        float* Crow = C + (size_t)(m0 + row) * D_ + n0;
        *(float4*)(Crow + tx*4)      = make_float4(acc[i][0],acc[i][1],acc[i][2],acc[i][3]);
        *(float4*)(Crow + 64 + tx*4) = make_float4(acc[i][4],acc[i][5],acc[i][6],acc[i][7]);
    }
}

// t = featIn @ Mw[r,layer]   (16384 x 768 x 768, NN), z = r
__global__ void __launch_bounds__(256) k_tf(const float* __restrict__ feature, int layer) {
    const int r = blockIdx.z;
    const float* A = (layer == 0) ? feature : (g_feat1 + (size_t)r * B_ * N_ * D_);
    const float* W = g_Mw + (size_t)(r * L_ + layer) * D_ * D_;
    float* C = g_t + (size_t)r * B_ * N_ * D_;
    const int m0 = blockIdx.x * 128, n0 = blockIdx.y * 128;

    __shared__ float As[8][128];
    __shared__ float Bs[8][128];
    float acc[8][8] = {};
    const int tid = threadIdx.x, tx = tid & 15, ty = tid >> 4;
    const int la_row = tid >> 1, la_k4 = (tid & 1) * 4;
    const int lb_k = tid >> 5, lb_n4 = (tid & 31) * 4;

    for (int k0 = 0; k0 < D_; k0 += 8) {
        float4 a4 = *(const float4*)(A + (size_t)(m0 + la_row) * D_ + k0 + la_k4);
        As[la_k4+0][la_row] = a4.x; As[la_k4+1][la_row] = a4.y;
        As[la_k4+2][la_row] = a4.z; As[la_k4+3][la_row] = a4.w;
        float4 b4 = *(const float4*)(W + (size_t)(k0 + lb_k) * D_ + n0 + lb_n4);
        *(float4*)&Bs[lb_k][lb_n4] = b4;
        __syncthreads();
        #pragma unroll
        for (int kk = 0; kk < 8; kk++) {
            float4 a0 = *(float4*)&As[kk][ty*4];
            float4 a1 = *(float4*)&As[kk][64+ty*4];
            float4 b0 = *(float4*)&Bs[kk][tx*4];
            float4 b1 = *(float4*)&Bs[kk][64+tx*4];
            float av[8] = {a0.x,a0.y,a0.z,a0.w,a1.x,a1.y,a1.z,a1.w};
            float bv[8] = {b0.x,b0.y,b0.z,b0.w,b1.x,b1.y,b1.z,b1.w};
            #pragma unroll
            for (int i = 0; i < 8; i++)
                #pragma unroll
                for (int j = 0; j < 8; j++)
                    acc[i][j] = fmaf(av[i], bv[j], acc[i][j]);
        }
        __syncthreads();
    }
    #pragma unroll
    for (int i = 0; i < 8; i++) {
        const int row = (i < 4) ? (ty*4 + i) : (64 + ty*4 + i - 4);
        float* Crow = C + (size_t)(m0 + row) * D_ + n0;
        *(float4*)(Crow + tx*4)      = make_float4(acc[i][0],acc[i][1],acc[i][2],acc[i][3]);
        *(float4*)(Crow + 64 + tx*4) = make_float4(acc[i][4],acc[i][5],acc[i][6],acc[i][7]);
    }
}

// logits = t[rb] @ featB[rb]^T / sqrt(D); gate epilogue + deterministic row-sum
// partials. layer 0: store full gate; layer 1: store only column 511.
__global__ void __launch_bounds__(256) k_gate(const float* __restrict__ pmask,
                                              const float* __restrict__ feature,
                                              int layer) {
    const int z = blockIdx.z;           // rb
    const int b = z % B_;
    const float* A  = g_t + (size_t)z * N_ * D_;
    const float* Bm = (layer == 0) ? (feature + (size_t)b * N_ * D_)
                                   : (g_feat1 + (size_t)z * N_ * D_);
    const int i0 = blockIdx.x * 128, j0 = blockIdx.y * 128, jt = blockIdx.y;

    __shared__ float As[8][128];
    __shared__ float Bs[8][128];
    float acc[8][8] = {};
    const int tid = threadIdx.x, tx = tid & 15, ty = tid >> 4;
    const int la_row = tid >> 1, la_k4 = (tid & 1) * 4;

    for (int k0 = 0; k0 < D_; k0 += 8) {
        float4 a4 = *(const float4*)(A + (size_t)(i0 + la_row) * D_ + k0 + la_k4);
        As[la_k4+0][la_row] = a4.x; As[la_k4+1][la_row] = a4.y;
        As[la_k4+2][la_row] = a4.z; As[la_k4+3][la_row] = a4.w;
        float4 b4 = *(const float4*)(Bm + (size_t)(j0 + la_row) * D_ + k0 + la_k4);
        Bs[la_k4+0][la_row] = b4.x; Bs[la_k4+1][la_row] = b4.y;
        Bs[la_k4+2][la_row] = b4.z; Bs[la_k4+3][la_row] = b4.w;
        __syncthreads();
        #pragma unroll
        for (int kk = 0; kk < 8; kk++) {
            float4 a0 = *(float4*)&As[kk][ty*4];
            float4 a1 = *(float4*)&As[kk][64+ty*4];
            float4 b0 = *(float4*)&Bs[kk][tx*4];
            float4 b1 = *(float4*)&Bs[kk][64+tx*4];
            float av[8] = {a0.x,a0.y,a0.z,a0.w,a1.x,a1.y,a1.z,a1.w};
            float bv[8] = {b0.x,b0.y,b0.z,b0.w,b1.x,b1.y,b1.z,b1.w};
            #pragma unroll
            for (int i = 0; i < 8; i++)
                #pragma unroll
                for (int j = 0; j < 8; j++)
                    acc[i][j] = fmaf(av[i], bv[j], acc[i][j]);
        }
        __syncthreads();
    }

    int ro[8], co[8];
    #pragma unroll
    for (int i = 0; i < 8; i++) {
        ro[i] = (i < 4) ? (ty*4 + i) : (64 + ty*4 + i - 4);
        co[i] = (i < 4) ? (tx*4 + i) : (64 + tx*4 + i - 4);
    }
    float pmi[8], pmj[8];
    #pragma unroll
    for (int i = 0; i < 8; i++) {
        pmi[i] = pmask[b*N_ + i0 + ro[i]];
        pmj[i] = pmask[b*N_ + j0 + co[i]];
    }
    float* degp = (layer == 0) ? g_degp : g_degp2;

    #pragma unroll
    for (int i = 0; i < 8; i++) {
        float gv[8];
        float rs = 0.f;
        #pragma unroll
        for (int j = 0; j < 8; j++) {
            float s = acc[i][j] * ISD;
            float p = 1.f / (1.f + expf(-s));
            float g = fminf(fmaxf(fmaf(p, 1.2f, -0.1f), 0.f), 1.f) * pmi[i] * pmj[j];
            gv[j] = g;
            rs += g;
        }
        if (layer == 0) {
            float* Crow = g_gate + (size_t)z * N_ * N_ + (size_t)(i0 + ro[i]) * N_ + j0;
            *(float4*)(Crow + tx*4)      = make_float4(gv[0],gv[1],gv[2],gv[3]);
            *(float4*)(Crow + 64 + tx*4) = make_float4(gv[4],gv[5],gv[6],gv[7]);
        } else {
            #pragma unroll
            for (int j = 0; j < 8; j++)
                if (j0 + co[j] == N_ - 1) g_gcol2[z*N_ + i0 + ro[i]] = gv[j];
        }
        // deterministic butterfly over the 16 lanes sharing this row group
        rs += __shfl_xor_sync(0xffffffffu, rs, 1);
        rs += __shfl_xor_sync(0xffffffffu, rs, 2);
        rs += __shfl_xor_sync(0xffffffffu, rs, 4);
        rs += __shfl_xor_sync(0xffffffffu, rs, 8);
        if (tx == 0) degp[(size_t)(z*N_ + i0 + ro[i]) * 4 + jt] = rs;
    }
}

// dis = deg > 0 ? deg^-1/2 : 0   (sums the 4 j-tile partials; deterministic)
__global__ void k_dis(int layer) {
    const int i = blockIdx.x * blockDim.x + threadIdx.x;
    if (i >= RB_ * N_) return;
    const float* degp = (layer == 0) ? g_degp : g_degp2;
    float* dis        = (layer == 0) ? g_disv : g_dis2;
    float d = (degp[i*4+0] + degp[i*4+1]) + (degp[i*4+2] + degp[i*4+3]);
    dis[i] = (d > 0.f) ? rsqrtf(d) : 0.f;
}

// feat1[j,d] = dis[j] * sum_i (gate[i,j]*dis[i]) * feature[b,i,d]
__global__ void __launch_bounds__(256) k_prop(const float* __restrict__ feature) {
    const int z = blockIdx.z;
    const int b = z % B_;
    const int j0 = blockIdx.x * 128, d0 = blockIdx.y * 128;
    const float* G = g_gate + (size_t)z * N_ * N_;
    const float* F = feature + (size_t)b * N_ * D_;
    const float* dis = g_disv + (size_t)z * N_;

    __shared__ float As[8][128];
    __shared__ float Bs[8][128];
    float acc[8][8] = {};
    const int tid = threadIdx.x, tx = tid & 15, ty = tid >> 4;
    const int lk = tid >> 5, lc4 = (tid & 31) * 4;

    for (int k0 = 0; k0 < N_; k0 += 8) {
        float dv = dis[k0 + lk];
        float4 a4 = *(const float4*)(G + (size_t)(k0 + lk) * N_ + j0 + lc4);
        a4.x *= dv; a4.y *= dv; a4.z *= dv; a4.w *= dv;
        *(float4*)&As[lk][lc4] = a4;
        float4 b4 = *(const float4*)(F + (size_t)(k0 + lk) * D_ + d0 + lc4);
        *(float4*)&Bs[lk][lc4] = b4;
        __syncthreads();
        #pragma unroll
        for (int kk = 0; kk < 8; kk++) {
            float4 a0 = *(float4*)&As[kk][ty*4];
            float4 a1 = *(float4*)&As[kk][64+ty*4];
            float4 b0 = *(float4*)&Bs[kk][tx*4];
            float4 b1 = *(float4*)&Bs[kk][64+tx*4];
            float av[8] = {a0.x,a0.y,a0.z,a0.w,a1.x,a1.y,a1.z,a1.w};
            float bv[8] = {b0.x,b0.y,b0.z,b0.w,b1.x,b1.y,b1.z,b1.w};
            #pragma unroll
            for (int i = 0; i < 8; i++)
                #pragma unroll
                for (int j = 0; j < 8; j++)
                    acc[i][j] = fmaf(av[i], bv[j], acc[i][j]);
        }
        __syncthreads();
    }
    #pragma unroll
    for (int i = 0; i < 8; i++) {
        const int row = (i < 4) ? (ty*4 + i) : (64 + ty*4 + i - 4);
        const float dj = dis[j0 + row];
        float* Crow = g_feat1 + (size_t)z * N_ * D_ + (size_t)(j0 + row) * D_ + d0;
        *(float4*)(Crow + tx*4)      = make_float4(acc[i][0]*dj,acc[i][1]*dj,acc[i][2]*dj,acc[i][3]*dj);
        *(float4*)(Crow + 64 + tx*4) = make_float4(acc[i][4]*dj,acc[i][5]*dj,acc[i][6]*dj,acc[i][7]*dj);
    }
}

// feat2 at node 511 only: node2[d] = dis2[511] * sum_i dis2[i]*gcol2[i]*feat1[i,d]
__global__ void __launch_bounds__(768) k_node2() {
    const int z = blockIdx.x;
    __shared__ float w[N_];
    const int tid = threadIdx.x;
    if (tid < N_) w[tid] = g_dis2[z*N_ + tid] * g_gcol2[z*N_ + tid];
    __syncthreads();
    const float disj = g_dis2[z*N_ + (N_-1)];
    const float* F = g_feat1 + (size_t)z * N_ * D_;
    float acc = 0.f;
    #pragma unroll 4
    for (int i = 0; i < N_; i++)
        acc = fmaf(w[i], F[(size_t)i * D_ + tid], acc);
    g_node2[(size_t)z * D_ + tid] = disj * acc;
}

// Per (r,b): retain gating over {feature, feat1, feat2} at node 511, then MLP.
__global__ void __launch_bounds__(256) k_head(const float* __restrict__ feature,
                                              const float* __restrict__ proj_w,
                                              const float* __restrict__ proj_b,
                                              const float* __restrict__ fc1_w,
                                              const float* __restrict__ fc1_b,
                                              const float* __restrict__ fc2_w,
                                              const float* __restrict__ fc2_b,
                                              const float* __restrict__ fcf_w,
                                              const float* __restrict__ fcf_b,
                                              float* __restrict__ out) {
    const int z = blockIdx.x;
    const int r = z / B_, b = z % B_;
    const int tid = threadIdx.x;
    __shared__ float f0[D_], f1[D_], f2[D_], xs[D_];
    __shared__ float h1[FH_], h2[FH_];
    __shared__ float red[32];

    const float* pw = proj_w + r * D_;
    float s0 = 0.f, s1 = 0.f, s2 = 0.f;
    for (int d = tid; d < D_; d += 256) {
        float a  = feature[((size_t)b * N_ + (N_-1)) * D_ + d];
        float c1 = g_feat1[(size_t)z * N_ * D_ + (size_t)(N_-1) * D_ + d];
        float c2 = g_node2[(size_t)z * D_ + d];
        float w  = pw[d];
        f0[d] = a; f1[d] = c1; f2[d] = c2;
        s0 = fmaf(a, w, s0); s1 = fmaf(c1, w, s1); s2 = fmaf(c2, w, s2);
    }
    // deterministic block reductions
    #pragma unroll
    for (int m = 16; m > 0; m >>= 1) {
        s0 += __shfl_xor_sync(0xffffffffu, s0, m);
        s1 += __shfl_xor_sync(0xffffffffu, s1, m);
        s2 += __shfl_xor_sync(0xffffffffu, s2, m);
    }
    if ((tid & 31) == 0) { red[(tid>>5)*3+0] = s0; red[(tid>>5)*3+1] = s1; red[(tid>>5)*3+2] = s2; }
    __syncthreads();
    if (tid == 0) {
        float t0 = 0.f, t1 = 0.f, t2 = 0.f;
        for (int w = 0; w < 8; w++) { t0 += red[w*3+0]; t1 += red[w*3+1]; t2 += red[w*3+2]; }
        red[24] = t0; red[25] = t1; red[26] = t2;
    }
    __syncthreads();
    const float pb = proj_b[r];
    const float rt0 = 1.f / (1.f + expf(-(red[24] + pb)));
    const float rt1 = 1.f / (1.f + expf(-(red[25] + pb)));
    const float rt2 = 1.f / (1.f + expf(-(red[26] + pb)));
    __syncthreads();
    for (int d = tid; d < D_; d += 256)
        xs[d] = rt0 * f0[d] + rt1 * f1[d] + rt2 * f2[d];
    __syncthreads();

    // fc1: h1 = relu(xs @ fc1_w^T + b)
    {
        const float* Wr = fc1_w + (size_t)(r * FH_ + tid) * D_;
        float acc = fc1_b[r * FH_ + tid];
        #pragma unroll 4
        for (int d = 0; d < D_; d++) acc = fmaf(xs[d], Wr[d], acc);
        h1[tid] = fmaxf(acc, 0.f);
    }
    __syncthreads();
    // fc2
    {
        const float* Wr = fc2_w + (size_t)(r * FH_ + tid) * FH_;
        float acc = fc2_b[r * FH_ + tid];
        #pragma unroll 4
        for (int h = 0; h < FH_; h++) acc = fmaf(h1[h], Wr[h], acc);
        h2[tid] = fmaxf(acc, 0.f);
    }
    __syncthreads();
    // fcf -> out[b, r, c]
    if (tid < NC_) {
        const float* Wr = fcf_w + (size_t)(r * NC_ + tid) * FH_;
        float acc = fcf_b[r * NC_ + tid];
        for (int g = 0; g < FH_; g++) acc = fmaf(h2[g], Wr[g], acc);
        out[((size_t)b * NBR_ + r) * NC_ + tid] = acc;
    }
}

extern "C" void kernel_launch(void* const* d_in, const int* in_sizes, int n_in,
                              void* d_out, int out_size) {
    const float* pmask   = (const float*)d_in[0];
    const float* feature = (const float*)d_in[1];
    const float* Wq      = (const float*)d_in[2];
    const float* Wk      = (const float*)d_in[3];
    const float* proj_w  = (const float*)d_in[4];
    const float* proj_b  = (const float*)d_in[5];
    const float* fc1_w   = (const float*)d_in[6];
    const float* fc1_b   = (const float*)d_in[7];
    const float* fc2_w   = (const float*)d_in[8];
    const float* fc2_b   = (const float*)d_in[9];
    const float* fcf_w   = (const float*)d_in[10];
    const float* fcf_b   = (const float*)d_in[11];
    float* out = (float*)d_out;

    // Mw = Wq @ Wk^T for all 8 (branch, layer) pairs
    k_mw<<<dim3(6, 6, NBR_*L_), 256>>>(Wq, Wk);

    // ---- layer 0 ----
    k_tf  <<<dim3(128, 6, NBR_), 256>>>(feature, 0);
    k_gate<<<dim3(4, 4, RB_),    256>>>(pmask, feature, 0);
    k_dis <<<(RB_*N_)/256,       256>>>(0);
    k_prop<<<dim3(4, 6, RB_),    256>>>(feature);

    // ---- layer 1 ----
    k_tf  <<<dim3(128, 6, NBR_), 256>>>(feature, 1);
    k_gate<<<dim3(4, 4, RB_),    256>>>(pmask, feature, 1);
    k_dis <<<(RB_*N_)/256,       256>>>(1);
    k_node2<<<RB_, 768>>>();

    // ---- head ----
    k_head<<<RB_, 256>>>(feature, proj_w, proj_b, fc1_w, fc1_b,
                         fc2_w, fc2_b, fcf_w, fcf_b, out);
}

// round 4
// speedup vs baseline: 1.0025x; 1.0025x over previous
#include <cuda_runtime.h>
#include <math.h>

#define B_   32
#define N_   512
#define D_   768
#define NBR_ 4
#define L_   2
#define FH_  256
#define NC_  2
#define RB_  (NBR_*B_)   // 128

#define ISD 0.0360843918243516f  // 1/sqrt(768)

// ---------------- scratch (device globals; allocation-free) ----------------
__device__ float g_Mw[NBR_*L_*D_*D_];       // Wq @ Wk^T per (branch,layer)
__device__ float g_t[NBR_*B_*N_*D_];        // feat @ Mw
__device__ float g_gate[NBR_*B_*N_*N_];     // layer-1 gate (adj)
__device__ float g_feat1[NBR_*B_*N_*D_];    // layer-1 propagated features
__device__ float g_degp [RB_*N_*4];         // layer-1 degree partials (per j-tile)
__device__ float g_disv [RB_*N_];           // layer-1 D^-1/2
__device__ float g_degp2[RB_*N_*4];         // layer-2 degree partials
__device__ float g_dis2 [RB_*N_];           // layer-2 D^-1/2
__device__ float g_gcol2[RB_*N_];           // layer-2 gate column j=511
__device__ float g_node2[RB_*D_];           // layer-2 node-511 features

// ---------------------------------------------------------------------------
// Common 128x128 tile, 256 threads, 8x8 per thread, K-tile 8.
// Thread map: tx = tid&15, ty = tid>>4.
// Rows owned: ty*4+i (i<4), 64+ty*4+(i-4). Cols same with tx.
// ---------------------------------------------------------------------------

// Mw[z] = Wq_mat[z] @ Wk_mat[z]^T   (768x768x768, NT), z in [0,8)
__global__ void __launch_bounds__(256) k_mw(const float* __restrict__ Wq,
                                            const float* __restrict__ Wk) {
    const int z = blockIdx.z;
    const float* A  = Wq + (size_t)z * D_ * D_;
    const float* Bm = Wk + (size_t)z * D_ * D_;
    float* C = g_Mw + (size_t)z * D_ * D_;
    const int m0 = blockIdx.x * 128, n0 = blockIdx.y * 128;

    __shared__ float As[8][128];
    __shared__ float Bs[8][128];
    float acc[8][8] = {};
    const int tid = threadIdx.x, tx = tid & 15, ty = tid >> 4;
    const int la_row = tid >> 1, la_k4 = (tid & 1) * 4;

    for (int k0 = 0; k0 < D_; k0 += 8) {
        float4 a4 = *(const float4*)(A + (size_t)(m0 + la_row) * D_ + k0 + la_k4);
        As[la_k4+0][la_row] = a4.x; As[la_k4+1][la_row] = a4.y;
        As[la_k4+2][la_row] = a4.z; As[la_k4+3][la_row] = a4.w;
        float4 b4 = *(const float4*)(Bm + (size_t)(n0 + la_row) * D_ + k0 + la_k4);
        Bs[la_k4+0][la_row] = b4.x; Bs[la_k4+1][la_row] = b4.y;
        Bs[la_k4+2][la_row] = b4.z; Bs[la_k4+3][la_row] = b4.w;
        __syncthreads();
        #pragma unroll
        for (int kk = 0; kk < 8; kk++) {
            float4 a0 = *(float4*)&As[kk][ty*4];
            float4 a1 = *(float4*)&As[kk][64+ty*4];
            float4 b0 = *(float4*)&Bs[kk][tx*4];
            float4 b1 = *(float4*)&Bs[kk][64+tx*4];
            float av[8] = {a0.x,a0.y,a0.z,a0.w,a1.x,a1.y,a1.z,a1.w};
            float bv[8] = {b0.x,b0.y,b0.z,b0.w,b1.x,b1.y,b1.z,b1.w};
            #pragma unroll
            for (int i = 0; i < 8; i++)
                #pragma unroll
                for (int j = 0; j < 8; j++)
                    acc[i][j] = fmaf(av[i], bv[j], acc[i][j]);
        }
        __syncthreads();
    }
    #pragma unroll
    for (int i = 0; i < 8; i++) {
        const int row = (i < 4) ? (ty*4 + i) : (64 + ty*4 + i - 4);
        float* Crow = C + (size_t)(m0 + row) * D_ + n0;
        *(float4*)(Crow + tx*4)      = make_float4(acc[i][0],acc[i][1],acc[i][2],acc[i][3]);
        *(float4*)(Crow + 64 + tx*4) = make_float4(acc[i][4],acc[i][5],acc[i][6],acc[i][7]);
    }
}

// t = featIn @ Mw[r,layer]   (16384 x 768 x 768, NN), z = r
__global__ void __launch_bounds__(256) k_tf(const float* __restrict__ feature, int layer) {
    const int r = blockIdx.z;
    const float* A = (layer == 0) ? feature : (g_feat1 + (size_t)r * B_ * N_ * D_);
    const float* W = g_Mw + (size_t)(r * L_ + layer) * D_ * D_;
    float* C = g_t + (size_t)r * B_ * N_ * D_;
    const int m0 = blockIdx.x * 128, n0 = blockIdx.y * 128;

    __shared__ float As[8][128];
    __shared__ float Bs[8][128];
    float acc[8][8] = {};
    const int tid = threadIdx.x, tx = tid & 15, ty = tid >> 4;
    const int la_row = tid >> 1, la_k4 = (tid & 1) * 4;
    const int lb_k = tid >> 5, lb_n4 = (tid & 31) * 4;

    for (int k0 = 0; k0 < D_; k0 += 8) {
        float4 a4 = *(const float4*)(A + (size_t)(m0 + la_row) * D_ + k0 + la_k4);
        As[la_k4+0][la_row] = a4.x; As[la_k4+1][la_row] = a4.y;
        As[la_k4+2][la_row] = a4.z; As[la_k4+3][la_row] = a4.w;
        float4 b4 = *(const float4*)(W + (size_t)(k0 + lb_k) * D_ + n0 + lb_n4);
        *(float4*)&Bs[lb_k][lb_n4] = b4;
        __syncthreads();
        #pragma unroll
        for (int kk = 0; kk < 8; kk++) {
            float4 a0 = *(float4*)&As[kk][ty*4];
            float4 a1 = *(float4*)&As[kk][64+ty*4];
            float4 b0 = *(float4*)&Bs[kk][tx*4];
            float4 b1 = *(float4*)&Bs[kk][64+tx*4];
            float av[8] = {a0.x,a0.y,a0.z,a0.w,a1.x,a1.y,a1.z,a1.w};
            float bv[8] = {b0.x,b0.y,b0.z,b0.w,b1.x,b1.y,b1.z,b1.w};
            #pragma unroll
            for (int i = 0; i < 8; i++)
                #pragma unroll
                for (int j = 0; j < 8; j++)
                    acc[i][j] = fmaf(av[i], bv[j], acc[i][j]);
        }
        __syncthreads();
    }
    #pragma unroll
    for (int i = 0; i < 8; i++) {
        const int row = (i < 4) ? (ty*4 + i) : (64 + ty*4 + i - 4);
        float* Crow = C + (size_t)(m0 + row) * D_ + n0;
        *(float4*)(Crow + tx*4)      = make_float4(acc[i][0],acc[i][1],acc[i][2],acc[i][3]);
        *(float4*)(Crow + 64 + tx*4) = make_float4(acc[i][4],acc[i][5],acc[i][6],acc[i][7]);
    }
}

// logits = t[rb] @ featB[rb]^T / sqrt(D); gate epilogue + deterministic row-sum
// partials. layer 0: store full gate; layer 1: store only column 511.
__global__ void __launch_bounds__(256) k_gate(const float* __restrict__ pmask,
                                              const float* __restrict__ feature,
                                              int layer) {
    const int z = blockIdx.z;           // rb
    const int b = z % B_;
    const float* A  = g_t + (size_t)z * N_ * D_;
    const float* Bm = (layer == 0) ? (feature + (size_t)b * N_ * D_)
                                   : (g_feat1 + (size_t)z * N_ * D_);
    const int i0 = blockIdx.x * 128, j0 = blockIdx.y * 128, jt = blockIdx.y;

    __shared__ float As[8][128];
    __shared__ float Bs[8][128];
    float acc[8][8] = {};
    const int tid = threadIdx.x, tx = tid & 15, ty = tid >> 4;
    const int la_row = tid >> 1, la_k4 = (tid & 1) * 4;

    for (int k0 = 0; k0 < D_; k0 += 8) {
        float4 a4 = *(const float4*)(A + (size_t)(i0 + la_row) * D_ + k0 + la_k4);
        As[la_k4+0][la_row] = a4.x; As[la_k4+1][la_row] = a4.y;
        As[la_k4+2][la_row] = a4.z; As[la_k4+3][la_row] = a4.w;
        float4 b4 = *(const float4*)(Bm + (size_t)(j0 + la_row) * D_ + k0 + la_k4);
        Bs[la_k4+0][la_row] = b4.x; Bs[la_k4+1][la_row] = b4.y;
        Bs[la_k4+2][la_row] = b4.z; Bs[la_k4+3][la_row] = b4.w;
        __syncthreads();
        #pragma unroll
        for (int kk = 0; kk < 8; kk++) {
            float4 a0 = *(float4*)&As[kk][ty*4];
            float4 a1 = *(float4*)&As[kk][64+ty*4];
            float4 b0 = *(float4*)&Bs[kk][tx*4];
            float4 b1 = *(float4*)&Bs[kk][64+tx*4];
            float av[8] = {a0.x,a0.y,a0.z,a0.w,a1.x,a1.y,a1.z,a1.w};
            float bv[8] = {b0.x,b0.y,b0.z,b0.w,b1.x,b1.y,b1.z,b1.w};
            #pragma unroll
            for (int i = 0; i < 8; i++)
                #pragma unroll
                for (int j = 0; j < 8; j++)
                    acc[i][j] = fmaf(av[i], bv[j], acc[i][j]);
        }
        __syncthreads();
    }

    int ro[8], co[8];
    #pragma unroll
    for (int i = 0; i < 8; i++) {
        ro[i] = (i < 4) ? (ty*4 + i) : (64 + ty*4 + i - 4);
        co[i] = (i < 4) ? (tx*4 + i) : (64 + tx*4 + i - 4);
    }
    float pmi[8], pmj[8];
    #pragma unroll
    for (int i = 0; i < 8; i++) {
        pmi[i] = pmask[b*N_ + i0 + ro[i]];
        pmj[i] = pmask[b*N_ + j0 + co[i]];
    }
    float* degp = (layer == 0) ? g_degp : g_degp2;

    #pragma unroll
    for (int i = 0; i < 8; i++) {
        float gv[8];
        float rs = 0.f;
        #pragma unroll
        for (int j = 0; j < 8; j++) {
            float s = acc[i][j] * ISD;
            float p = 1.f / (1.f + expf(-s));
            float g = fminf(fmaxf(fmaf(p, 1.2f, -0.1f), 0.f), 1.f) * pmi[i] * pmj[j];
            gv[j] = g;
            rs += g;
        }
        if (layer == 0) {
            float* Crow = g_gate + (size_t)z * N_ * N_ + (size_t)(i0 + ro[i]) * N_ + j0;
            *(float4*)(Crow + tx*4)      = make_float4(gv[0],gv[1],gv[2],gv[3]);
            *(float4*)(Crow + 64 + tx*4) = make_float4(gv[4],gv[5],gv[6],gv[7]);
        } else {
            #pragma unroll
            for (int j = 0; j < 8; j++)
                if (j0 + co[j] == N_ - 1) g_gcol2[z*N_ + i0 + ro[i]] = gv[j];
        }
        // deterministic butterfly over the 16 lanes sharing this row group
        rs += __shfl_xor_sync(0xffffffffu, rs, 1);
        rs += __shfl_xor_sync(0xffffffffu, rs, 2);
        rs += __shfl_xor_sync(0xffffffffu, rs, 4);
        rs += __shfl_xor_sync(0xffffffffu, rs, 8);
        if (tx == 0) degp[(size_t)(z*N_ + i0 + ro[i]) * 4 + jt] = rs;
    }
}

// dis = deg > 0 ? deg^-1/2 : 0   (sums the 4 j-tile partials; deterministic)
__global__ void k_dis(int layer) {
    const int i = blockIdx.x * blockDim.x + threadIdx.x;
    if (i >= RB_ * N_) return;
    const float* degp = (layer == 0) ? g_degp : g_degp2;
    float* dis        = (layer == 0) ? g_disv : g_dis2;
    float d = (degp[i*4+0] + degp[i*4+1]) + (degp[i*4+2] + degp[i*4+3]);
    dis[i] = (d > 0.f) ? rsqrtf(d) : 0.f;
}

// feat1[j,d] = dis[j] * sum_i (gate[i,j]*dis[i]) * feature[b,i,d]
__global__ void __launch_bounds__(256) k_prop(const float* __restrict__ feature) {
    const int z = blockIdx.z;
    const int b = z % B_;
    const int j0 = blockIdx.x * 128, d0 = blockIdx.y * 128;
    const float* G = g_gate + (size_t)z * N_ * N_;
    const float* F = feature + (size_t)b * N_ * D_;
    const float* dis = g_disv + (size_t)z * N_;

    __shared__ float As[8][128];
    __shared__ float Bs[8][128];
    float acc[8][8] = {};
    const int tid = threadIdx.x, tx = tid & 15, ty = tid >> 4;
    const int lk = tid >> 5, lc4 = (tid & 31) * 4;

    for (int k0 = 0; k0 < N_; k0 += 8) {
        float dv = dis[k0 + lk];
        float4 a4 = *(const float4*)(G + (size_t)(k0 + lk) * N_ + j0 + lc4);
        a4.x *= dv; a4.y *= dv; a4.z *= dv; a4.w *= dv;
        *(float4*)&As[lk][lc4] = a4;
        float4 b4 = *(const float4*)(F + (size_t)(k0 + lk) * D_ + d0 + lc4);
        *(float4*)&Bs[lk][lc4] = b4;
        __syncthreads();
        #pragma unroll
        for (int kk = 0; kk < 8; kk++) {
            float4 a0 = *(float4*)&As[kk][ty*4];
            float4 a1 = *(float4*)&As[kk][64+ty*4];
            float4 b0 = *(float4*)&Bs[kk][tx*4];
            float4 b1 = *(float4*)&Bs[kk][64+tx*4];
            float av[8] = {a0.x,a0.y,a0.z,a0.w,a1.x,a1.y,a1.z,a1.w};
            float bv[8] = {b0.x,b0.y,b0.z,b0.w,b1.x,b1.y,b1.z,b1.w};
            #pragma unroll
            for (int i = 0; i < 8; i++)
                #pragma unroll
                for (int j = 0; j < 8; j++)
                    acc[i][j] = fmaf(av[i], bv[j], acc[i][j]);
        }
        __syncthreads();
    }
    #pragma unroll
    for (int i = 0; i < 8; i++) {
        const int row = (i < 4) ? (ty*4 + i) : (64 + ty*4 + i - 4);
        const float dj = dis[j0 + row];
        float* Crow = g_feat1 + (size_t)z * N_ * D_ + (size_t)(j0 + row) * D_ + d0;
        *(float4*)(Crow + tx*4)      = make_float4(acc[i][0]*dj,acc[i][1]*dj,acc[i][2]*dj,acc[i][3]*dj);
        *(float4*)(Crow + 64 + tx*4) = make_float4(acc[i][4]*dj,acc[i][5]*dj,acc[i][6]*dj,acc[i][7]*dj);
    }
}

// feat2 at node 511 only: node2[d] = dis2[511] * sum_i dis2[i]*gcol2[i]*feat1[i,d]
__global__ void __launch_bounds__(768) k_node2() {
    const int z = blockIdx.x;
    __shared__ float w[N_];
    const int tid = threadIdx.x;
    if (tid < N_) w[tid] = g_dis2[z*N_ + tid] * g_gcol2[z*N_ + tid];
    __syncthreads();
    const float disj = g_dis2[z*N_ + (N_-1)];
    const float* F = g_feat1 + (size_t)z * N_ * D_;
    float acc = 0.f;
    #pragma unroll 4
    for (int i = 0; i < N_; i++)
        acc = fmaf(w[i], F[(size_t)i * D_ + tid], acc);
    g_node2[(size_t)z * D_ + tid] = disj * acc;
}

// Per (r,b): retain gating over {feature, feat1, feat2} at node 511, then MLP.
__global__ void __launch_bounds__(256) k_head(const float* __restrict__ feature,
                                              const float* __restrict__ proj_w,
                                              const float* __restrict__ proj_b,
                                              const float* __restrict__ fc1_w,
                                              const float* __restrict__ fc1_b,
                                              const float* __restrict__ fc2_w,
                                              const float* __restrict__ fc2_b,
                                              const float* __restrict__ fcf_w,
                                              const float* __restrict__ fcf_b,
                                              float* __restrict__ out) {
    const int z = blockIdx.x;
    const int r = z / B_, b = z % B_;
    const int tid = threadIdx.x;
    __shared__ float f0[D_], f1[D_], f2[D_], xs[D_];
    __shared__ float h1[FH_], h2[FH_];
    __shared__ float red[32];

    const float* pw = proj_w + r * D_;
    float s0 = 0.f, s1 = 0.f, s2 = 0.f;
    for (int d = tid; d < D_; d += 256) {
        float a  = feature[((size_t)b * N_ + (N_-1)) * D_ + d];
        float c1 = g_feat1[(size_t)z * N_ * D_ + (size_t)(N_-1) * D_ + d];
        float c2 = g_node2[(size_t)z * D_ + d];
        float w  = pw[d];
        f0[d] = a; f1[d] = c1; f2[d] = c2;
        s0 = fmaf(a, w, s0); s1 = fmaf(c1, w, s1); s2 = fmaf(c2, w, s2);
    }
    // deterministic block reductions
    #pragma unroll
    for (int m = 16; m > 0; m >>= 1) {
        s0 += __shfl_xor_sync(0xffffffffu, s0, m);
        s1 += __shfl_xor_sync(0xffffffffu, s1, m);
        s2 += __shfl_xor_sync(0xffffffffu, s2, m);
    }
    if ((tid & 31) == 0) { red[(tid>>5)*3+0] = s0; red[(tid>>5)*3+1] = s1; red[(tid>>5)*3+2] = s2; }
    __syncthreads();
    if (tid == 0) {
        float t0 = 0.f, t1 = 0.f, t2 = 0.f;
        for (int w = 0; w < 8; w++) { t0 += red[w*3+0]; t1 += red[w*3+1]; t2 += red[w*3+2]; }
        red[24] = t0; red[25] = t1; red[26] = t2;
    }
    __syncthreads();
    const float pb = proj_b[r];
    const float rt0 = 1.f / (1.f + expf(-(red[24] + pb)));
    const float rt1 = 1.f / (1.f + expf(-(red[25] + pb)));
    const float rt2 = 1.f / (1.f + expf(-(red[26] + pb)));
    __syncthreads();
    for (int d = tid; d < D_; d += 256)
        xs[d] = rt0 * f0[d] + rt1 * f1[d] + rt2 * f2[d];
    __syncthreads();

    // fc1: h1 = relu(xs @ fc1_w^T + b)
    {
        const float* Wr = fc1_w + (size_t)(r * FH_ + tid) * D_;
        float acc = fc1_b[r * FH_ + tid];
        #pragma unroll 4
        for (int d = 0; d < D_; d++) acc = fmaf(xs[d], Wr[d], acc);
        h1[tid] = fmaxf(acc, 0.f);
    }
    __syncthreads();
    // fc2
    {
        const float* Wr = fc2_w + (size_t)(r * FH_ + tid) * FH_;
        float acc = fc2_b[r * FH_ + tid];
        #pragma unroll 4
        for (int h = 0; h < FH_; h++) acc = fmaf(h1[h], Wr[h], acc);
        h2[tid] = fmaxf(acc, 0.f);
    }
    __syncthreads();
    // fcf -> out[b, r, c]
    if (tid < NC_) {
        const float* Wr = fcf_w + (size_t)(r * NC_ + tid) * FH_;
        float acc = fcf_b[r * NC_ + tid];
        for (int g = 0; g < FH_; g++) acc = fmaf(h2[g], Wr[g], acc);
        out[((size_t)b * NBR_ + r) * NC_ + tid] = acc;
    }
}

extern "C" void kernel_launch(void* const* d_in, const int* in_sizes, int n_in,
                              void* d_out, int out_size) {
    const float* pmask   = (const float*)d_in[0];
    const float* feature = (const float*)d_in[1];
    const float* Wq      = (const float*)d_in[2];
    const float* Wk      = (const float*)d_in[3];
    const float* proj_w  = (const float*)d_in[4];
    const float* proj_b  = (const float*)d_in[5];
    const float* fc1_w   = (const float*)d_in[6];
    const float* fc1_b   = (const float*)d_in[7];
    const float* fc2_w   = (const float*)d_in[8];
    const float* fc2_b   = (const float*)d_in[9];
    const float* fcf_w   = (const float*)d_in[10];
    const float* fcf_b   = (const float*)d_in[11];
    float* out = (float*)d_out;

    // Mw = Wq @ Wk^T for all 8 (branch, layer) pairs
    k_mw<<<dim3(6, 6, NBR_*L_), 256>>>(Wq, Wk);

    // ---- layer 0 ----
    k_tf  <<<dim3(128, 6, NBR_), 256>>>(feature, 0);
    k_gate<<<dim3(4, 4, RB_),    256>>>(pmask, feature, 0);
    k_dis <<<(RB_*N_)/256,       256>>>(0);
    k_prop<<<dim3(4, 6, RB_),    256>>>(feature);

    // ---- layer 1 ----
    k_tf  <<<dim3(128, 6, NBR_), 256>>>(feature, 1);
    k_gate<<<dim3(4, 4, RB_),    256>>>(pmask, feature, 1);
    k_dis <<<(RB_*N_)/256,       256>>>(1);
    k_node2<<<RB_, 768>>>();

    // ---- head ----
    k_head<<<RB_, 256>>>(feature, proj_w, proj_b, fc1_w, fc1_b,
                         fc2_w, fc2_b, fcf_w, fcf_b, out);
}

// round 6
// speedup vs baseline: 2.5263x; 2.5201x over previous
#include <cuda_runtime.h>
#include <cuda_bf16.h>
#include <math.h>
#include <stdint.h>

#define B_   32
#define N_   512
#define D_   768
#define NBR_ 4
#define L_   2
#define FH_  256
#define NC_  2
#define RB_  (NBR_*B_)   // 128

#define ISD 0.0360843918243516f  // 1/sqrt(768)

// ---------------- scratch (device globals; allocation-free) ----------------
__device__ float g_Mt[NBR_*L_*D_*D_];      // (Wq@Wk^T)^T = Wk@Wq^T  [n][k]
__device__ float g_t[NBR_*B_*N_*D_];       // feat @ Mw
__device__ float g_gateT[RB_*N_*N_];       // layer-1 gate TRANSPOSED [z][j][i]
__device__ float g_feat1[RB_*N_*D_];       // layer-1 propagated features
__device__ float g_featT[B_*D_*N_];        // feature transposed [b][d][i]
__device__ float g_degp [RB_*N_*16];       // layer-1 degree partials
__device__ float g_disv [RB_*N_];          // layer-1 D^-1/2
__device__ float g_degp2[RB_*N_*16];       // layer-2 degree partials
__device__ float g_dis2 [RB_*N_];          // layer-2 D^-1/2
__device__ float g_gcol2[RB_*N_];          // layer-2 gate column j=511
__device__ float g_node2[RB_*D_];          // layer-2 node-511 features

// ===================== warp-MMA (bf16 HMMA) machinery =======================
// 128x128 C-tile, K-chunk 64, 256 threads = 8 warps in 2(m) x 4(n).
// Each warp: 64x32 accumulators = 16 fragments of m16n8, 4 fp32 regs each.
// Split-bf16 3-term: Ah*Bh + Al*Bh + Ah*Bl.

#define KPAD    72                       // bf16 elems per smem row (144B, 16B mult)
#define ATILE_B (128*KPAD*2)             // 18432 bytes per tile buffer
#define OFF_AHI 0
#define OFF_ALO (ATILE_B)
#define OFF_BHI (2*ATILE_B)
#define OFF_BLO (3*ATILE_B)
#define SMEM_REQ (4*ATILE_B)             // 73728 B (gate reuses it for transpose)

__device__ __forceinline__ uint32_t smem_u32(const void* p) {
    uint32_t a;
    asm("{ .reg .u64 t; cvta.to.shared.u64 t, %1; cvt.u32.u64 %0, t; }"
        : "=r"(a) : "l"(p));
    return a;
}

__device__ __forceinline__ void ldsm4(uint32_t r[4], uint32_t addr) {
    asm volatile("ldmatrix.sync.aligned.m8n8.x4.shared.b16 {%0,%1,%2,%3}, [%4];"
                 : "=r"(r[0]), "=r"(r[1]), "=r"(r[2]), "=r"(r[3]) : "r"(addr));
}

__device__ __forceinline__ void mma_bf16(float c[4], const uint32_t a[4],
                                         uint32_t b0, uint32_t b1) {
    asm volatile(
        "mma.sync.aligned.m16n8k16.row.col.f32.bf16.bf16.f32 "
        "{%0,%1,%2,%3}, {%4,%5,%6,%7}, {%8,%9}, {%0,%1,%2,%3};"
        : "+f"(c[0]), "+f"(c[1]), "+f"(c[2]), "+f"(c[3])
        : "r"(a[0]), "r"(a[1]), "r"(a[2]), "r"(a[3]), "r"(b0), "r"(b1));
}

// load a 128x64 fp32 tile (rows of src, leading dim ld, k-window k0), split
// into bf16 hi/lo, store row-major with KPAD stride. Optional k-scale.
__device__ __forceinline__ void load_split(const float* __restrict__ src, int ld,
                                           int k0, char* smb, int off_hi, int off_lo,
                                           const float* __restrict__ ksc) {
    const int tid = threadIdx.x;
    __nv_bfloat16* hi = (__nv_bfloat16*)(smb + off_hi);
    __nv_bfloat16* lo = (__nv_bfloat16*)(smb + off_lo);
    #pragma unroll
    for (int g = 0; g < 8; g++) {
        int idx = g * 256 + tid;           // 2048 = 128 rows * 16 quads
        int row = idx >> 4;
        int k4  = (idx & 15) << 2;
        float4 v = *(const float4*)(src + (size_t)row * ld + k0 + k4);
        if (ksc) {
            v.x *= ksc[k0 + k4];     v.y *= ksc[k0 + k4 + 1];
            v.z *= ksc[k0 + k4 + 2]; v.w *= ksc[k0 + k4 + 3];
        }
        __nv_bfloat16 h0 = __float2bfloat16(v.x), h1 = __float2bfloat16(v.y),
                      h2 = __float2bfloat16(v.z), h3 = __float2bfloat16(v.w);
        __nv_bfloat16 l0 = __float2bfloat16(v.x - __bfloat162float(h0)),
                      l1 = __float2bfloat16(v.y - __bfloat162float(h1)),
                      l2 = __float2bfloat16(v.z - __bfloat162float(h2)),
                      l3 = __float2bfloat16(v.w - __bfloat162float(h3));
        __nv_bfloat162 ha = __halves2bfloat162(h0, h1), hb = __halves2bfloat162(h2, h3);
        __nv_bfloat162 la = __halves2bfloat162(l0, l1), lb = __halves2bfloat162(l2, l3);
        uint2 hp, lp;
        hp.x = *(uint32_t*)&ha; hp.y = *(uint32_t*)&hb;
        lp.x = *(uint32_t*)&la; lp.y = *(uint32_t*)&lb;
        *(uint2*)(hi + row * KPAD + k4) = hp;
        *(uint2*)(lo + row * KPAD + k4) = lp;
    }
}

// one 64-K chunk of split-bf16 MMAs; acc[16][4] per thread
__device__ __forceinline__ void mma_chunk(uint32_t sb, float (*acc)[4]) {
    const int lane = threadIdx.x & 31;
    const int wid  = threadIdx.x >> 5;
    const int wr = wid >> 2, wc = wid & 3;
    uint32_t aoff[4];
    #pragma unroll
    for (int mt = 0; mt < 4; mt++)
        aoff[mt] = (uint32_t)(((wr*64 + mt*16 + (lane & 7) + ((lane >> 3) & 1) * 8) * KPAD
                               + (lane >> 4) * 8) * 2);
    uint32_t boff[2];
    #pragma unroll
    for (int pr = 0; pr < 2; pr++)
        boff[pr] = (uint32_t)(((wc*32 + pr*16 + ((lane >> 4) & 1) * 8 + (lane & 7)) * KPAD
                               + ((lane >> 3) & 1) * 8) * 2);
    #pragma unroll
    for (int ks = 0; ks < 4; ks++) {
        const uint32_t kb = ks * 32;      // 16 bf16 = 32 bytes
        uint32_t A[4][4], Bv[4][2];
        // ---- Bh ----
        #pragma unroll
        for (int pr = 0; pr < 2; pr++) {
            uint32_t rr[4];
            ldsm4(rr, sb + OFF_BHI + boff[pr] + kb);
            Bv[pr*2][0] = rr[0]; Bv[pr*2][1] = rr[1];
            Bv[pr*2+1][0] = rr[2]; Bv[pr*2+1][1] = rr[3];
        }
        // ---- Ah * Bh ----
        #pragma unroll
        for (int mt = 0; mt < 4; mt++) ldsm4(A[mt], sb + OFF_AHI + aoff[mt] + kb);
        #pragma unroll
        for (int mt = 0; mt < 4; mt++)
            #pragma unroll
            for (int nt = 0; nt < 4; nt++)
                mma_bf16(acc[mt*4+nt], A[mt], Bv[nt][0], Bv[nt][1]);
        // ---- Al * Bh ----
        #pragma unroll
        for (int mt = 0; mt < 4; mt++) ldsm4(A[mt], sb + OFF_ALO + aoff[mt] + kb);
        #pragma unroll
        for (int mt = 0; mt < 4; mt++)
            #pragma unroll
            for (int nt = 0; nt < 4; nt++)
                mma_bf16(acc[mt*4+nt], A[mt], Bv[nt][0], Bv[nt][1]);
        // ---- Ah * Bl ----
        #pragma unroll
        for (int pr = 0; pr < 2; pr++) {
            uint32_t rr[4];
            ldsm4(rr, sb + OFF_BLO + boff[pr] + kb);
            Bv[pr*2][0] = rr[0]; Bv[pr*2][1] = rr[1];
            Bv[pr*2+1][0] = rr[2]; Bv[pr*2+1][1] = rr[3];
        }
        #pragma unroll
        for (int mt = 0; mt < 4; mt++) ldsm4(A[mt], sb + OFF_AHI + aoff[mt] + kb);
        #pragma unroll
        for (int mt = 0; mt < 4; mt++)
            #pragma unroll
            for (int nt = 0; nt < 4; nt++)
                mma_bf16(acc[mt*4+nt], A[mt], Bv[nt][0], Bv[nt][1]);
    }
}

// full mainloop: C(128x128) = sum over kchunks of A[m,k]*B[n,k]
__device__ __forceinline__ void mma_main(const float* __restrict__ A, int lda,
                                         const float* __restrict__ Bm, int ldb,
                                         int kchunks, const float* __restrict__ ksc,
                                         char* smb, float (*acc)[4]) {
    uint32_t sb = smem_u32(smb);
    for (int c = 0; c < kchunks; c++) {
        __syncthreads();
        load_split(A,  lda, c * 64, smb, OFF_AHI, OFF_ALO, ksc);
        load_split(Bm, ldb, c * 64, smb, OFF_BHI, OFF_BLO, (const float*)0);
        __syncthreads();
        mma_chunk(sb, acc);
    }
}

// store acc to gmem C (row-major, ldc), optional per-row scale vector
__device__ __forceinline__ void store_acc(float (*acc)[4], float* __restrict__ C,
                                          int ldc, const float* __restrict__ rscale) {
    const int lane = threadIdx.x & 31;
    const int wid  = threadIdx.x >> 5;
    const int wr = wid >> 2, wc = wid & 3;
    #pragma unroll
    for (int mt = 0; mt < 4; mt++) {
        const int r0 = wr*64 + mt*16 + (lane >> 2);
        const float s0 = rscale ? rscale[r0] : 1.f;
        const float s1 = rscale ? rscale[r0 + 8] : 1.f;
        #pragma unroll
        for (int nt = 0; nt < 4; nt++) {
            const int cn = wc*32 + nt*8 + (lane & 3) * 2;
            float* f = acc[mt*4+nt];
            *(float2*)(C + (size_t)r0 * ldc + cn)       = make_float2(f[0]*s0, f[1]*s0);
            *(float2*)(C + (size_t)(r0+8) * ldc + cn)   = make_float2(f[2]*s1, f[3]*s1);
        }
    }
}

// ============================ kernels =======================================

// featT[b][d][i] = feature[b][i][d]
__global__ void __launch_bounds__(256) k_tr(const float* __restrict__ f) {
    __shared__ float t[32][33];
    const int b = blockIdx.z;
    const int i0 = blockIdx.x * 32, d0 = blockIdx.y * 32;
    const int tx = threadIdx.x & 31, ty = threadIdx.x >> 5;
    #pragma unroll
    for (int s = 0; s < 32; s += 8)
        t[ty + s][tx] = f[((size_t)b * N_ + i0 + ty + s) * D_ + d0 + tx];
    __syncthreads();
    #pragma unroll
    for (int s = 0; s < 32; s += 8)
        g_featT[((size_t)b * D_ + d0 + ty + s) * N_ + i0 + tx] = t[tx][ty + s];
}

// Mt[z] = Wk[z] @ Wq[z]^T
__global__ void __launch_bounds__(256, 2)
k_mw_tc(const float* __restrict__ Wk, const float* __restrict__ Wq) {
    extern __shared__ char smb[];
    const int z = blockIdx.z, m0 = blockIdx.x * 128, n0 = blockIdx.y * 128;
    float acc[16][4] = {};
    mma_main(Wk + (size_t)z * D_ * D_ + (size_t)m0 * D_, D_,
             Wq + (size_t)z * D_ * D_ + (size_t)n0 * D_, D_,
             12, (const float*)0, smb, acc);
    store_acc(acc, g_Mt + (size_t)z * D_ * D_ + (size_t)m0 * D_ + n0, D_, (const float*)0);
}

// t = featIn @ Mw[r,layer]
__global__ void __launch_bounds__(256, 2)
k_tf_tc(const float* __restrict__ feature, int layer) {
    extern __shared__ char smb[];
    const int r = blockIdx.z, m0 = blockIdx.x * 128, n0 = blockIdx.y * 128;
    const float* Abase = layer ? (g_feat1 + (size_t)r * B_ * N_ * D_) : feature;
    float acc[16][4] = {};
    mma_main(Abase + (size_t)m0 * D_, D_,
             g_Mt + (size_t)(r * L_ + layer) * D_ * D_ + (size_t)n0 * D_, D_,
             12, (const float*)0, smb, acc);
    store_acc(acc, g_t + ((size_t)r * B_ * N_ + m0) * D_ + n0, D_, (const float*)0);
}

// logits = t @ featB^T; gate epilogue + deterministic row-sum partials.
// layer0: transpose gate tile in smem, write gateT coalesced; layer1: column 511.
__global__ void __launch_bounds__(256, 2)
k_gate_tc(const float* __restrict__ pmask, const float* __restrict__ feature,
          int layer) {
    extern __shared__ char smb[];
    const int z = blockIdx.z, b = z & (B_ - 1);
    const int i0 = blockIdx.x * 128, j0 = blockIdx.y * 128, jt = blockIdx.y;
    const float* Bbase = layer ? (g_feat1 + (size_t)z * N_ * D_)
                               : (feature + (size_t)b * N_ * D_);
    float acc[16][4] = {};
    mma_main(g_t + (size_t)z * N_ * D_ + (size_t)i0 * D_, D_,
             Bbase + (size_t)j0 * D_, D_, 12, (const float*)0, smb, acc);

    const int lane = threadIdx.x & 31;
    const int wid  = threadIdx.x >> 5;
    const int wr = wid >> 2, wc = wid & 3;
    float* sT = (float*)smb;               // [128][132] j-major transpose buffer
    __syncthreads();                        // tiles done; reuse smem

    float* degp = layer ? g_degp2 : g_degp;
    #pragma unroll
    for (int mt = 0; mt < 4; mt++) {
        const int r0 = wr*64 + mt*16 + (lane >> 2);
        const float pmi0 = pmask[b*N_ + i0 + r0];
        const float pmi1 = pmask[b*N_ + i0 + r0 + 8];
        float rs0 = 0.f, rs1 = 0.f;
        #pragma unroll
        for (int nt = 0; nt < 4; nt++) {
            const int cn = wc*32 + nt*8 + (lane & 3) * 2;
            const float pj0 = pmask[b*N_ + j0 + cn];
            const float pj1 = pmask[b*N_ + j0 + cn + 1];
            float* f = acc[mt*4+nt];
            #pragma unroll
            for (int e = 0; e < 4; e++) {
                const float pmi = (e < 2) ? pmi0 : pmi1;
                const float pmj = (e & 1) ? pj1 : pj0;
                const float s = f[e] * ISD;
                const float p = 1.f / (1.f + __expf(-s));
                const float g = fminf(fmaxf(fmaf(p, 1.2f, -0.1f), 0.f), 1.f) * pmi * pmj;
                const int jl = cn + (e & 1);
                const int il = (e < 2) ? r0 : (r0 + 8);
                if (layer == 0) {
                    sT[jl * 132 + il] = g;
                } else if (j0 + jl == N_ - 1) {
                    g_gcol2[z*N_ + i0 + il] = g;
                }
                if (e < 2) rs0 += g; else rs1 += g;
            }
        }
        rs0 += __shfl_xor_sync(0xffffffffu, rs0, 1);
        rs0 += __shfl_xor_sync(0xffffffffu, rs0, 2);
        rs1 += __shfl_xor_sync(0xffffffffu, rs1, 1);
        rs1 += __shfl_xor_sync(0xffffffffu, rs1, 2);
        if ((lane & 3) == 0) {
            degp[((size_t)(z*N_ + i0 + r0)) * 16 + jt*4 + wc]     = rs0;
            degp[((size_t)(z*N_ + i0 + r0 + 8)) * 16 + jt*4 + wc] = rs1;
        }
    }
    if (layer == 0) {
        __syncthreads();
        // coalesced copy sT -> g_gateT[z][j0+jl][i0+il]
        const int tid = threadIdx.x;
        #pragma unroll
        for (int it = 0; it < 16; it++) {
            int idx = it * 256 + tid;       // 4096 float4s
            int jl = idx >> 5, c4 = (idx & 31) * 4;
            float4 v = *(float4*)(sT + jl * 132 + c4);
            *(float4*)(g_gateT + (size_t)z * N_ * N_ + (size_t)(j0 + jl) * N_ + i0 + c4) = v;
        }
    }
}

// dis = deg > 0 ? deg^-1/2 : 0  (sums the 16 partials deterministically)
__global__ void k_dis(int layer) {
    const int i = blockIdx.x * blockDim.x + threadIdx.x;
    if (i >= RB_ * N_) return;
    const float* degp = layer ? g_degp2 : g_degp;
    float* dis        = layer ? g_dis2  : g_disv;
    float d = 0.f;
    #pragma unroll
    for (int p = 0; p < 16; p++) d += degp[(size_t)i * 16 + p];
    dis[i] = (d > 0.f) ? rsqrtf(d) : 0.f;
}

// feat1[j][d] = dis[j] * sum_i (gateT[j][i]*dis[i]) * featT[b][d][i]
__global__ void __launch_bounds__(256, 2)
k_prop_tc() {
    extern __shared__ char smb[];
    const int z = blockIdx.z, b = z & (B_ - 1);
    const int j0 = blockIdx.x * 128, d0 = blockIdx.y * 128;
    const float* dis = g_disv + (size_t)z * N_;
    float acc[16][4] = {};
    mma_main(g_gateT + (size_t)z * N_ * N_ + (size_t)j0 * N_, N_,
             g_featT + (size_t)b * D_ * N_ + (size_t)d0 * N_, N_,
             8, dis, smb, acc);
    store_acc(acc, g_feat1 + ((size_t)z * N_ + j0) * D_ + d0, D_, dis + j0);
}

// feat2 at node 511 only
__global__ void __launch_bounds__(768) k_node2() {
    const int z = blockIdx.x;
    __shared__ float w[N_];
    const int tid = threadIdx.x;
    if (tid < N_) w[tid] = g_dis2[z*N_ + tid] * g_gcol2[z*N_ + tid];
    __syncthreads();
    const float disj = g_dis2[z*N_ + (N_-1)];
    const float* F = g_feat1 + (size_t)z * N_ * D_;
    float acc = 0.f;
    #pragma unroll 4
    for (int i = 0; i < N_; i++)
        acc = fmaf(w[i], F[(size_t)i * D_ + tid], acc);
    g_node2[(size_t)z * D_ + tid] = disj * acc;
}

// Per (r,b): retain gating at node 511, then 3-layer MLP head.
__global__ void __launch_bounds__(256) k_head(const float* __restrict__ feature,
                                              const float* __restrict__ proj_w,
                                              const float* __restrict__ proj_b,
                                              const float* __restrict__ fc1_w,
                                              const float* __restrict__ fc1_b,
                                              const float* __restrict__ fc2_w,
                                              const float* __restrict__ fc2_b,
                                              const float* __restrict__ fcf_w,
                                              const float* __restrict__ fcf_b,
                                              float* __restrict__ out) {
    const int z = blockIdx.x;
    const int r = z / B_, b = z % B_;
    const int tid = threadIdx.x;
    __shared__ float f0[D_], f1[D_], f2[D_], xs[D_];
    __shared__ float h1[FH_], h2[FH_];
    __shared__ float red[32];

    const float* pw = proj_w + r * D_;
    float s0 = 0.f, s1 = 0.f, s2 = 0.f;
    for (int d = tid; d < D_; d += 256) {
        float a  = feature[((size_t)b * N_ + (N_-1)) * D_ + d];
        float c1 = g_feat1[((size_t)z * N_ + (N_-1)) * D_ + d];
        float c2 = g_node2[(size_t)z * D_ + d];
        float w  = pw[d];
        f0[d] = a; f1[d] = c1; f2[d] = c2;
        s0 = fmaf(a, w, s0); s1 = fmaf(c1, w, s1); s2 = fmaf(c2, w, s2);
    }
    #pragma unroll
    for (int m = 16; m > 0; m >>= 1) {
        s0 += __shfl_xor_sync(0xffffffffu, s0, m);
        s1 += __shfl_xor_sync(0xffffffffu, s1, m);
        s2 += __shfl_xor_sync(0xffffffffu, s2, m);
    }
    if ((tid & 31) == 0) { red[(tid>>5)*3+0] = s0; red[(tid>>5)*3+1] = s1; red[(tid>>5)*3+2] = s2; }
    __syncthreads();
    if (tid == 0) {
        float t0 = 0.f, t1 = 0.f, t2 = 0.f;
        for (int w = 0; w < 8; w++) { t0 += red[w*3+0]; t1 += red[w*3+1]; t2 += red[w*3+2]; }
        red[24] = t0; red[25] = t1; red[26] = t2;
    }
    __syncthreads();
    const float pb = proj_b[r];
    const float rt0 = 1.f / (1.f + expf(-(red[24] + pb)));
    const float rt1 = 1.f / (1.f + expf(-(red[25] + pb)));
    const float rt2 = 1.f / (1.f + expf(-(red[26] + pb)));
    __syncthreads();
    for (int d = tid; d < D_; d += 256)
        xs[d] = rt0 * f0[d] + rt1 * f1[d] + rt2 * f2[d];
    __syncthreads();

    {
        const float* Wr = fc1_w + (size_t)(r * FH_ + tid) * D_;
        float acc = fc1_b[r * FH_ + tid];
        #pragma unroll 4
        for (int d = 0; d < D_; d++) acc = fmaf(xs[d], Wr[d], acc);
        h1[tid] = fmaxf(acc, 0.f);
    }
    __syncthreads();
    {
        const float* Wr = fc2_w + (size_t)(r * FH_ + tid) * FH_;
        float acc = fc2_b[r * FH_ + tid];
        #pragma unroll 4
        for (int h = 0; h < FH_; h++) acc = fmaf(h1[h], Wr[h], acc);
        h2[tid] = fmaxf(acc, 0.f);
    }
    __syncthreads();
    if (tid < NC_) {
        const float* Wr = fcf_w + (size_t)(r * NC_ + tid) * FH_;
        float acc = fcf_b[r * NC_ + tid];
        for (int g = 0; g < FH_; g++) acc = fmaf(h2[g], Wr[g], acc);
        out[((size_t)b * NBR_ + r) * NC_ + tid] = acc;
    }
}

extern "C" void kernel_launch(void* const* d_in, const int* in_sizes, int n_in,
                              void* d_out, int out_size) {
    const float* pmask   = (const float*)d_in[0];
    const float* feature = (const float*)d_in[1];
    const float* Wq      = (const float*)d_in[2];
    const float* Wk      = (const float*)d_in[3];
    const float* proj_w  = (const float*)d_in[4];
    const float* proj_b  = (const float*)d_in[5];
    const float* fc1_w   = (const float*)d_in[6];
    const float* fc1_b   = (const float*)d_in[7];
    const float* fc2_w   = (const float*)d_in[8];
    const float* fc2_b   = (const float*)d_in[9];
    const float* fcf_w   = (const float*)d_in[10];
    const float* fcf_b   = (const float*)d_in[11];
    float* out = (float*)d_out;

    static int attr_done = 0;
    if (!attr_done) {
        cudaFuncSetAttribute(k_mw_tc,   cudaFuncAttributeMaxDynamicSharedMemorySize, SMEM_REQ);
        cudaFuncSetAttribute(k_tf_tc,   cudaFuncAttributeMaxDynamicSharedMemorySize, SMEM_REQ);
        cudaFuncSetAttribute(k_gate_tc, cudaFuncAttributeMaxDynamicSharedMemorySize, SMEM_REQ);
        cudaFuncSetAttribute(k_prop_tc, cudaFuncAttributeMaxDynamicSharedMemorySize, SMEM_REQ);
        attr_done = 1;
    }

    // feature transpose (prop B-operand) + Mw^T for all 8 (branch,layer)
    k_tr   <<<dim3(16, 24, B_), 256>>>(feature);
    k_mw_tc<<<dim3(6, 6, NBR_*L_), 256, SMEM_REQ>>>(Wk, Wq);

    // ---- layer 0 ----
    k_tf_tc  <<<dim3(128, 6, NBR_), 256, SMEM_REQ>>>(feature, 0);
    k_gate_tc<<<dim3(4, 4, RB_),    256, SMEM_REQ>>>(pmask, feature, 0);
    k_dis    <<<(RB_*N_)/256, 256>>>(0);
    k_prop_tc<<<dim3(4, 6, RB_),    256, SMEM_REQ>>>();

    // ---- layer 1 ----
    k_tf_tc  <<<dim3(128, 6, NBR_), 256, SMEM_REQ>>>(feature, 1);
    k_gate_tc<<<dim3(4, 4, RB_),    256, SMEM_REQ>>>(pmask, feature, 1);
    k_dis    <<<(RB_*N_)/256, 256>>>(1);
    k_node2  <<<RB_, 768>>>();

    // ---- head ----
    k_head<<<RB_, 256>>>(feature, proj_w, proj_b, fc1_w, fc1_b,
                         fc2_w, fc2_b, fcf_w, fcf_b, out);
}